// round 6
// baseline (speedup 1.0000x reference)
#include <cuda_runtime.h>
#include <cuda_bf16.h>
#include <math.h>

// ---------------------------------------------------------------------------
// GCN: 3x GCNConv (1->128->64->32) + global mean pool + FC (32->10), N=65536,
// E=524288, 64 graphs.
//
// NOTE: edge_index / batch are int32 on device (JAX x64-disabled default
// silently downcasts the reference's jnp.int64).
//
// Key algebra: with dinv = rsqrt(deg+1),
//   layer(h) = relu( dinv .* ( Scatter_{src->dst}(y) + y ) + b ),  y = dinv .* (h @ W)
// Layer 1 is rank-1 (in_feat = 1): the scatter is scalar.
// Scatter accumulators are initialized with y (self-loop term) so no zeroing
// of the big buffers is needed.
// ---------------------------------------------------------------------------

#define N_NODES 65536
#define N_GRAPHS 64

__device__ float g_deg [N_NODES];
__device__ float g_dinv[N_NODES];
__device__ float g_s   [N_NODES];   // dinv * x   (layer-1 scalar "y")
__device__ float g_t   [N_NODES];   // scatter of g_s
__device__ float g_y2  [N_NODES * 64];
__device__ float g_z2  [N_NODES * 64];
__device__ float g_y3  [N_NODES * 32];
__device__ float g_z3  [N_NODES * 32];
__device__ float g_pool[N_GRAPHS * 32];
__device__ float g_cnt [N_GRAPHS];

// ---- K0: zero the small accumulators -------------------------------------
__global__ void k0_zero() {
    int i = blockIdx.x * blockDim.x + threadIdx.x;
    if (i < N_NODES) { g_deg[i] = 0.f; g_t[i] = 0.f; }
    if (i < N_GRAPHS * 32) g_pool[i] = 0.f;
    if (i < N_GRAPHS) g_cnt[i] = 0.f;
}

// ---- K1: degree (count of dst) --------------------------------------------
__global__ void k1_deg(const int* __restrict__ ei, int E) {
    int e = blockIdx.x * blockDim.x + threadIdx.x;
    if (e >= E) return;
    int dst = ei[E + e];
    atomicAdd(&g_deg[dst], 1.0f);
}

// ---- K2: dinv and layer-1 scalar y ----------------------------------------
__global__ void k2_dinv(const float* __restrict__ x, int n) {
    int i = blockIdx.x * blockDim.x + threadIdx.x;
    if (i >= n) return;
    float d = g_deg[i] + 1.0f;
    float dinv = rsqrtf(d);
    g_dinv[i] = dinv;
    g_s[i] = dinv * x[i];
}

// ---- K3: layer-1 scalar scatter -------------------------------------------
__global__ void k3_scatter1(const int* __restrict__ ei, int E) {
    int e = blockIdx.x * blockDim.x + threadIdx.x;
    if (e >= E) return;
    int src = ei[e];
    int dst = ei[E + e];
    atomicAdd(&g_t[dst], g_s[src]);
}

// ---- K4: fused  h1 = relu(a*W1+b1);  y2 = dinv*(h1@W2);  z2 init = y2 -----
// thread-per-node, 64 accumulators, W2 row broadcast from smem.
__global__ void __launch_bounds__(256) k4_layer12(
    const float* __restrict__ W1, const float* __restrict__ b1,
    const float* __restrict__ W2, int n)
{
    __shared__ float sW1[128];
    __shared__ float sb1[128];
    __shared__ float sW2[128 * 64];
    for (int t = threadIdx.x; t < 128 * 64; t += 256) sW2[t] = W2[t];
    if (threadIdx.x < 128) {
        sW1[threadIdx.x] = W1[threadIdx.x];
        sb1[threadIdx.x] = b1[threadIdx.x];
    }
    __syncthreads();

    int i = blockIdx.x * 256 + threadIdx.x;
    if (i >= n) return;
    float dinv = g_dinv[i];
    float a = dinv * (g_t[i] + g_s[i]);

    float acc[64];
#pragma unroll
    for (int j = 0; j < 64; j++) acc[j] = 0.f;

#pragma unroll 2
    for (int k = 0; k < 128; k++) {
        float h = fmaxf(fmaf(a, sW1[k], sb1[k]), 0.f);
        const float4* row = reinterpret_cast<const float4*>(&sW2[k * 64]);
#pragma unroll
        for (int j4 = 0; j4 < 16; j4++) {
            float4 w = row[j4];
            acc[4 * j4 + 0] = fmaf(h, w.x, acc[4 * j4 + 0]);
            acc[4 * j4 + 1] = fmaf(h, w.y, acc[4 * j4 + 1]);
            acc[4 * j4 + 2] = fmaf(h, w.z, acc[4 * j4 + 2]);
            acc[4 * j4 + 3] = fmaf(h, w.w, acc[4 * j4 + 3]);
        }
    }

    float4* y = reinterpret_cast<float4*>(&g_y2[(size_t)i * 64]);
    float4* z = reinterpret_cast<float4*>(&g_z2[(size_t)i * 64]);
#pragma unroll
    for (int j4 = 0; j4 < 16; j4++) {
        float4 v = make_float4(dinv * acc[4 * j4 + 0], dinv * acc[4 * j4 + 1],
                               dinv * acc[4 * j4 + 2], dinv * acc[4 * j4 + 3]);
        y[j4] = v;
        z[j4] = v;
    }
}

// ---- K5: layer-2 edge scatter (64 floats/edge, 16 threads/edge) -----------
__global__ void k5_scatter2(const int* __restrict__ ei, int E) {
    int t = blockIdx.x * blockDim.x + threadIdx.x;
    int e = t >> 4;
    int q = t & 15;
    if (e >= E) return;
    int src = __ldg(&ei[e]);
    int dst = __ldg(&ei[E + e]);
    const float4* ys = reinterpret_cast<const float4*>(g_y2 + (size_t)src * 64);
    float4 v = ys[q];
    float* zp = g_z2 + (size_t)dst * 64 + q * 4;
    atomicAdd(zp + 0, v.x);
    atomicAdd(zp + 1, v.y);
    atomicAdd(zp + 2, v.z);
    atomicAdd(zp + 3, v.w);
}

// ---- K6: fused  h2 = relu(dinv*z2+b2);  y3 = dinv*(h2@W3);  z3 init = y3 --
// warp-per-node: lane holds h2[lane], h2[lane+32]; shuffle-broadcast over k.
__global__ void __launch_bounds__(256) k6_layer3(
    const float* __restrict__ W3, const float* __restrict__ b2, int n)
{
    __shared__ float sW3[64 * 32];
    __shared__ float sb2[64];
    for (int t = threadIdx.x; t < 64 * 32; t += 256) sW3[t] = W3[t];
    if (threadIdx.x < 64) sb2[threadIdx.x] = b2[threadIdx.x];
    __syncthreads();

    int wid = (blockIdx.x * 256 + threadIdx.x) >> 5;
    int lane = threadIdx.x & 31;
    if (wid >= n) return;
    float dinv = g_dinv[wid];
    const float* zrow = g_z2 + (size_t)wid * 64;
    float h0 = fmaxf(fmaf(dinv, zrow[lane],      sb2[lane]),      0.f);
    float h1 = fmaxf(fmaf(dinv, zrow[lane + 32], sb2[lane + 32]), 0.f);

    float acc = 0.f;
#pragma unroll
    for (int k = 0; k < 32; k++) {
        float hk = __shfl_sync(0xffffffffu, h0, k);
        acc = fmaf(hk, sW3[k * 32 + lane], acc);
    }
#pragma unroll
    for (int k = 0; k < 32; k++) {
        float hk = __shfl_sync(0xffffffffu, h1, k);
        acc = fmaf(hk, sW3[(k + 32) * 32 + lane], acc);
    }
    float v = dinv * acc;
    g_y3[(size_t)wid * 32 + lane] = v;
    g_z3[(size_t)wid * 32 + lane] = v;
}

// ---- K7: layer-3 edge scatter (32 floats/edge, 8 threads/edge) ------------
__global__ void k7_scatter3(const int* __restrict__ ei, int E) {
    int t = blockIdx.x * blockDim.x + threadIdx.x;
    int e = t >> 3;
    int q = t & 7;
    if (e >= E) return;
    int src = __ldg(&ei[e]);
    int dst = __ldg(&ei[E + e]);
    const float4* ys = reinterpret_cast<const float4*>(g_y3 + (size_t)src * 32);
    float4 v = ys[q];
    float* zp = g_z3 + (size_t)dst * 32 + q * 4;
    atomicAdd(zp + 0, v.x);
    atomicAdd(zp + 1, v.y);
    atomicAdd(zp + 2, v.z);
    atomicAdd(zp + 3, v.w);
}

// ---- K8: h3 = relu(dinv*z3+b3); mean-pool accumulate -----------------------
__global__ void __launch_bounds__(256) k8_pool(
    const int* __restrict__ batch, const float* __restrict__ b3, int n)
{
    int wid = (blockIdx.x * 256 + threadIdx.x) >> 5;
    int lane = threadIdx.x & 31;
    if (wid >= n) return;
    float dinv = g_dinv[wid];
    float v = fmaxf(fmaf(dinv, g_z3[(size_t)wid * 32 + lane], __ldg(&b3[lane])), 0.f);
    int b = batch[wid];
    atomicAdd(&g_pool[b * 32 + lane], v);
    if (lane == 0) atomicAdd(&g_cnt[b], 1.0f);
}

// ---- K9: out = (pool/cnt) @ Wfc + bfc --------------------------------------
__global__ void k9_fc(const float* __restrict__ Wfc, const float* __restrict__ bfc,
                      float* __restrict__ out)
{
    int t = threadIdx.x;
    if (t >= N_GRAPHS * 10) return;
    int g = t / 10;
    int o = t % 10;
    float cnt = fmaxf(g_cnt[g], 1.0f);
    float s = 0.f;
#pragma unroll
    for (int k = 0; k < 32; k++)
        s = fmaf(g_pool[g * 32 + k], Wfc[k * 10 + o], s);
    out[t] = s / cnt + bfc[o];
}

// ---------------------------------------------------------------------------
extern "C" void kernel_launch(void* const* d_in, const int* in_sizes, int n_in,
                              void* d_out, int out_size)
{
    const float* x     = (const float*)d_in[0];
    const int*   ei    = (const int*)d_in[1];     // int32! (JAX x64 disabled)
    const int*   batch = (const int*)d_in[2];     // int32!
    const float* W1    = (const float*)d_in[3];
    const float* b1    = (const float*)d_in[4];
    const float* W2    = (const float*)d_in[5];
    const float* b2    = (const float*)d_in[6];
    const float* W3    = (const float*)d_in[7];
    const float* b3    = (const float*)d_in[8];
    const float* Wfc   = (const float*)d_in[9];
    const float* bfc   = (const float*)d_in[10];
    float* out = (float*)d_out;

    int n = in_sizes[0];          // 65536
    int E = in_sizes[1] / 2;      // 524288

    k0_zero    <<<(N_NODES + 255) / 256, 256>>>();
    k1_deg     <<<(E + 255) / 256, 256>>>(ei, E);
    k2_dinv    <<<(n + 255) / 256, 256>>>(x, n);
    k3_scatter1<<<(E + 255) / 256, 256>>>(ei, E);
    k4_layer12 <<<(n + 255) / 256, 256>>>(W1, b1, W2, n);
    k5_scatter2<<<(E * 16 + 255) / 256, 256>>>(ei, E);
    k6_layer3  <<<(n * 32 + 255) / 256, 256>>>(W3, b2, n);
    k7_scatter3<<<(E * 8 + 255) / 256, 256>>>(ei, E);
    k8_pool    <<<(n * 32 + 255) / 256, 256>>>(batch, b3, n);
    k9_fc      <<<1, 640>>>(Wfc, bfc, out);
}

// round 8
// speedup vs baseline: 1.4185x; 1.4185x over previous
#include <cuda_runtime.h>
#include <cuda_bf16.h>
#include <math.h>

// ---------------------------------------------------------------------------
// GCN: 3x GCNConv (1->128->64->32) + global mean pool + FC (32->10), N=65536,
// E=524288, 64 graphs.  edge_index / batch are int32 on device.
//
// Algebra: with dinv = rsqrt(deg+1),
//   layer(h) = relu( dinv .* ( Scatter(y) + y ) + b ),  y = dinv .* (h @ W)
// Layer 1 is rank-1 (in_feat = 1) -> scalar scatter.
// Scatter accumulators are initialized with y (self-loop term).
// Edge scatters use red.global.add.v4.f32 (1 LTS op / 16B).
// ---------------------------------------------------------------------------

#define N_NODES 65536
#define N_GRAPHS 64

__device__ float g_deg [N_NODES];
__device__ float g_dinv[N_NODES];
__device__ float g_s   [N_NODES];
__device__ float g_t   [N_NODES];
__device__ __align__(256) float g_y2  [N_NODES * 64];
__device__ __align__(256) float g_z2  [N_NODES * 64];
__device__ __align__(256) float g_y3  [N_NODES * 32];
__device__ __align__(256) float g_z3  [N_NODES * 32];
__device__ float g_pool[N_GRAPHS * 32];
__device__ float g_cnt [N_GRAPHS];

__device__ __forceinline__ void red_add_v4(float* p, float4 v) {
    asm volatile("red.global.add.v4.f32 [%0], {%1, %2, %3, %4};"
                 :: "l"(p), "f"(v.x), "f"(v.y), "f"(v.z), "f"(v.w) : "memory");
}

// ---- K0: zero the small accumulators -------------------------------------
__global__ void k0_zero() {
    int i = blockIdx.x * blockDim.x + threadIdx.x;
    if (i < N_NODES) { g_deg[i] = 0.f; g_t[i] = 0.f; }
    if (i < N_GRAPHS * 32) g_pool[i] = 0.f;
    if (i < N_GRAPHS) g_cnt[i] = 0.f;
}

// ---- K1: degree (count of dst) --------------------------------------------
__global__ void k1_deg(const int* __restrict__ ei, int E) {
    int e = blockIdx.x * blockDim.x + threadIdx.x;
    if (e >= E) return;
    atomicAdd(&g_deg[ei[E + e]], 1.0f);
}

// ---- K2: dinv, layer-1 scalar y, graph node counts -------------------------
__global__ void k2_dinv(const float* __restrict__ x, const int* __restrict__ batch, int n) {
    int i = blockIdx.x * blockDim.x + threadIdx.x;
    if (i >= n) return;
    float d = g_deg[i] + 1.0f;
    float dinv = rsqrtf(d);
    g_dinv[i] = dinv;
    g_s[i] = dinv * x[i];
    atomicAdd(&g_cnt[batch[i]], 1.0f);
}

// ---- K3: layer-1 scalar scatter -------------------------------------------
__global__ void k3_scatter1(const int* __restrict__ ei, int E) {
    int e = blockIdx.x * blockDim.x + threadIdx.x;
    if (e >= E) return;
    int src = ei[e];
    int dst = ei[E + e];
    atomicAdd(&g_t[dst], g_s[src]);
}

// ---- K4: fused  h1 = relu(a*W1+b1);  y2 = dinv*(h1@W2);  z2 init = y2 -----
__global__ void __launch_bounds__(256) k4_layer12(
    const float* __restrict__ W1, const float* __restrict__ b1,
    const float* __restrict__ W2, int n)
{
    __shared__ float sW1[128];
    __shared__ float sb1[128];
    __shared__ float sW2[128 * 64];
    for (int t = threadIdx.x; t < 128 * 64; t += 256) sW2[t] = W2[t];
    if (threadIdx.x < 128) {
        sW1[threadIdx.x] = W1[threadIdx.x];
        sb1[threadIdx.x] = b1[threadIdx.x];
    }
    __syncthreads();

    int i = blockIdx.x * 256 + threadIdx.x;
    if (i >= n) return;
    float dinv = g_dinv[i];
    float a = dinv * (g_t[i] + g_s[i]);

    float acc[64];
#pragma unroll
    for (int j = 0; j < 64; j++) acc[j] = 0.f;

#pragma unroll 2
    for (int k = 0; k < 128; k++) {
        float h = fmaxf(fmaf(a, sW1[k], sb1[k]), 0.f);
        const float4* row = reinterpret_cast<const float4*>(&sW2[k * 64]);
#pragma unroll
        for (int j4 = 0; j4 < 16; j4++) {
            float4 w = row[j4];
            acc[4 * j4 + 0] = fmaf(h, w.x, acc[4 * j4 + 0]);
            acc[4 * j4 + 1] = fmaf(h, w.y, acc[4 * j4 + 1]);
            acc[4 * j4 + 2] = fmaf(h, w.z, acc[4 * j4 + 2]);
            acc[4 * j4 + 3] = fmaf(h, w.w, acc[4 * j4 + 3]);
        }
    }

    float4* y = reinterpret_cast<float4*>(&g_y2[(size_t)i * 64]);
    float4* z = reinterpret_cast<float4*>(&g_z2[(size_t)i * 64]);
#pragma unroll
    for (int j4 = 0; j4 < 16; j4++) {
        float4 v = make_float4(dinv * acc[4 * j4 + 0], dinv * acc[4 * j4 + 1],
                               dinv * acc[4 * j4 + 2], dinv * acc[4 * j4 + 3]);
        y[j4] = v;
        z[j4] = v;
    }
}

// ---- K5: layer-2 edge scatter (64 floats/edge, 16 threads/edge, v4 red) ---
__global__ void k5_scatter2(const int* __restrict__ ei, int E) {
    int t = blockIdx.x * blockDim.x + threadIdx.x;
    int e = t >> 4;
    int q = t & 15;
    if (e >= E) return;
    int src = __ldg(&ei[e]);
    int dst = __ldg(&ei[E + e]);
    float4 v = reinterpret_cast<const float4*>(g_y2 + (size_t)src * 64)[q];
    red_add_v4(g_z2 + (size_t)dst * 64 + q * 4, v);
}

// ---- K6: fused  h2 = relu(dinv*z2+b2);  y3 = dinv*(h2@W3);  z3 init = y3 --
__global__ void __launch_bounds__(256) k6_layer3(
    const float* __restrict__ W3, const float* __restrict__ b2, int n)
{
    __shared__ float sW3[64 * 32];
    __shared__ float sb2[64];
    for (int t = threadIdx.x; t < 64 * 32; t += 256) sW3[t] = W3[t];
    if (threadIdx.x < 64) sb2[threadIdx.x] = b2[threadIdx.x];
    __syncthreads();

    int wid = (blockIdx.x * 256 + threadIdx.x) >> 5;
    int lane = threadIdx.x & 31;
    if (wid >= n) return;
    float dinv = g_dinv[wid];
    const float* zrow = g_z2 + (size_t)wid * 64;
    float h0 = fmaxf(fmaf(dinv, zrow[lane],      sb2[lane]),      0.f);
    float h1 = fmaxf(fmaf(dinv, zrow[lane + 32], sb2[lane + 32]), 0.f);

    float acc = 0.f;
#pragma unroll
    for (int k = 0; k < 32; k++) {
        float hk = __shfl_sync(0xffffffffu, h0, k);
        acc = fmaf(hk, sW3[k * 32 + lane], acc);
    }
#pragma unroll
    for (int k = 0; k < 32; k++) {
        float hk = __shfl_sync(0xffffffffu, h1, k);
        acc = fmaf(hk, sW3[(k + 32) * 32 + lane], acc);
    }
    float v = dinv * acc;
    g_y3[(size_t)wid * 32 + lane] = v;
    g_z3[(size_t)wid * 32 + lane] = v;
}

// ---- K7: layer-3 edge scatter (32 floats/edge, 8 threads/edge, v4 red) ----
__global__ void k7_scatter3(const int* __restrict__ ei, int E) {
    int t = blockIdx.x * blockDim.x + threadIdx.x;
    int e = t >> 3;
    int q = t & 7;
    if (e >= E) return;
    int src = __ldg(&ei[e]);
    int dst = __ldg(&ei[E + e]);
    float4 v = reinterpret_cast<const float4*>(g_y3 + (size_t)src * 32)[q];
    red_add_v4(g_z3 + (size_t)dst * 32 + q * 4, v);
}

// ---- K8: h3 = relu(dinv*z3+b3); segmented block pool (batch is sorted) -----
__global__ void __launch_bounds__(256) k8_pool(
    const int* __restrict__ batch, const float* __restrict__ b3, int n)
{
    __shared__ float sv[8][32];
    __shared__ int   sb[8];
    int warp = threadIdx.x >> 5;
    int lane = threadIdx.x & 31;
    int node = blockIdx.x * 8 + warp;

    float v = 0.f;
    int b = -1;
    if (node < n) {
        float dinv = g_dinv[node];
        v = fmaxf(fmaf(dinv, g_z3[(size_t)node * 32 + lane], __ldg(&b3[lane])), 0.f);
        b = batch[node];
    }
    sv[warp][lane] = v;
    if (lane == 0) sb[warp] = b;
    __syncthreads();

    if (threadIdx.x < 32) {
        int j = threadIdx.x;
        float run = 0.f;
        int prev = sb[0];
#pragma unroll
        for (int w = 0; w < 8; w++) {
            int bw = sb[w];
            if (bw != prev) {
                if (prev >= 0) atomicAdd(&g_pool[prev * 32 + j], run);
                run = 0.f;
                prev = bw;
            }
            run += sv[w][j];
        }
        if (prev >= 0) atomicAdd(&g_pool[prev * 32 + j], run);
    }
}

// ---- K9: out = (pool/cnt) @ Wfc + bfc --------------------------------------
__global__ void k9_fc(const float* __restrict__ Wfc, const float* __restrict__ bfc,
                      float* __restrict__ out)
{
    int t = threadIdx.x;
    if (t >= N_GRAPHS * 10) return;
    int g = t / 10;
    int o = t % 10;
    float cnt = fmaxf(g_cnt[g], 1.0f);
    float s = 0.f;
#pragma unroll
    for (int k = 0; k < 32; k++)
        s = fmaf(g_pool[g * 32 + k], Wfc[k * 10 + o], s);
    out[t] = s / cnt + bfc[o];
}

// ---------------------------------------------------------------------------
extern "C" void kernel_launch(void* const* d_in, const int* in_sizes, int n_in,
                              void* d_out, int out_size)
{
    const float* x     = (const float*)d_in[0];
    const int*   ei    = (const int*)d_in[1];     // int32 (JAX x64 disabled)
    const int*   batch = (const int*)d_in[2];     // int32
    const float* W1    = (const float*)d_in[3];
    const float* b1    = (const float*)d_in[4];
    const float* W2    = (const float*)d_in[5];
    const float* b2    = (const float*)d_in[6];
    const float* W3    = (const float*)d_in[7];
    const float* b3    = (const float*)d_in[8];
    const float* Wfc   = (const float*)d_in[9];
    const float* bfc   = (const float*)d_in[10];
    float* out = (float*)d_out;

    int n = in_sizes[0];          // 65536
    int E = in_sizes[1] / 2;      // 524288

    k0_zero    <<<(N_NODES + 255) / 256, 256>>>();
    k1_deg     <<<(E + 255) / 256, 256>>>(ei, E);
    k2_dinv    <<<(n + 255) / 256, 256>>>(x, batch, n);
    k3_scatter1<<<(E + 255) / 256, 256>>>(ei, E);
    k4_layer12 <<<(n + 255) / 256, 256>>>(W1, b1, W2, n);
    k5_scatter2<<<(E * 16 + 255) / 256, 256>>>(ei, E);
    k6_layer3  <<<(n * 32 + 255) / 256, 256>>>(W3, b2, n);
    k7_scatter3<<<(E * 8 + 255) / 256, 256>>>(ei, E);
    k8_pool    <<<(n + 7) / 8, 256>>>(batch, b3, n);
    k9_fc      <<<1, 640>>>(Wfc, bfc, out);
}